// round 1
// baseline (speedup 1.0000x reference)
#include <cuda_runtime.h>

#define N_NODES 50000
#define N_EDGES 640000
#define FDIM    128
#define OUT_DIM 16
#define BATCH   2
#define M_ROWS  (BATCH * N_NODES)   /* 100000 flattened rows */
#define EPSBN   1e-5f

// ---------------- scratch (device globals; no allocation allowed) -------------
__device__ __align__(128) float g_xw  [(size_t)M_ROWS * FDIM];  // GEMM outputs (both layers)
__device__ __align__(128) float g_agg [(size_t)M_ROWS * FDIM];  // scatter accumulator
__device__ __align__(128) float g_t   [(size_t)M_ROWS * FDIM];  // relu(conv) activations
__device__ __align__(128) float g_norm[N_EDGES];
__device__ __align__(128) float g_dinv[N_NODES];
__device__ __align__(128) float g_deg [N_NODES];
__device__ __align__(128) float g_W2p [FDIM * FDIM];
__device__ __align__(128) float g_cvec[FDIM];
__device__ __align__(128) float g_Wcp [FDIM * OUT_DIM];
__device__ __align__(128) float g_bcp [OUT_DIM];
__device__ __align__(128) float g_sum [FDIM];
__device__ __align__(128) float g_sq  [FDIM];

// ---------------- norm setup -------------------------------------------------
__global__ void k_init_deg(float* deg) {
    int i = blockIdx.x * blockDim.x + threadIdx.x;
    if (i < N_NODES) deg[i] = 1.0f;  // self-loop weight
}

__global__ void k_accum_deg(const float* __restrict__ ewp, const int* __restrict__ col,
                            float* deg) {
    int e = blockIdx.x * blockDim.x + threadIdx.x;
    if (e < N_EDGES) atomicAdd(&deg[col[e]], expf(ewp[e]));
}

__global__ void k_dinv(const float* __restrict__ deg, float* dinv) {
    int i = blockIdx.x * blockDim.x + threadIdx.x;
    if (i < N_NODES) {
        float d = deg[i];
        dinv[i] = (d > 0.f) ? rsqrtf(d) : 0.f;
    }
}

__global__ void k_norm(const float* __restrict__ ewp, const int* __restrict__ row,
                       const int* __restrict__ col, const float* __restrict__ dinv,
                       float* __restrict__ norm) {
    int e = blockIdx.x * blockDim.x + threadIdx.x;
    if (e < N_EDGES) norm[e] = dinv[row[e]] * expf(ewp[e]) * dinv[col[e]];
}

// ---------------- GEMM: C[M x128] = A[M x128] @ W[128x128] (+ cvec) ----------
// f32x2 packed-FMA GEMM. 256 threads, 64-row tiles, whole W in smem.
__global__ __launch_bounds__(256) void k_gemm128(const float* __restrict__ A,
                                                 const float* __restrict__ W,
                                                 const float* __restrict__ cvec,
                                                 float* __restrict__ C, int Mrows) {
    extern __shared__ float smem[];
    float* sW = smem;            // 128*128 floats = 64 KB
    float* sA = smem + 16384;    // 64*128 floats = 32 KB
    const int tid = threadIdx.x;

    {   // load W once per block
        const float4* W4 = (const float4*)W;
        float4* sW4 = (float4*)sW;
        #pragma unroll
        for (int i = 0; i < 16; i++) sW4[tid + i * 256] = W4[tid + i * 256];
    }

    const int tc = tid & 15;   // cols 8*tc .. 8*tc+7
    const int tr = tid >> 4;   // rows 4*tr .. 4*tr+3

    unsigned long long initc[4];
    if (cvec) {
        #pragma unroll
        for (int p = 0; p < 4; p++) {
            float2 cv2 = *(const float2*)(cvec + 8 * tc + 2 * p);
            asm("mov.b64 %0, {%1, %2};" : "=l"(initc[p]) : "f"(cv2.x), "f"(cv2.y));
        }
    } else {
        #pragma unroll
        for (int p = 0; p < 4; p++) initc[p] = 0ull;
    }

    const int ntiles = (Mrows + 63) >> 6;
    for (int tile = blockIdx.x; tile < ntiles; tile += gridDim.x) {
        const int base = tile << 6;
        __syncthreads();  // protect sA (and initial sW) before overwrite
        #pragma unroll
        for (int i = 0; i < 8; i++) {
            int f4 = tid + i * 256;          // 0..2047 float4 slots
            int r = f4 >> 5;
            int c4 = f4 & 31;
            int grow = base + r;
            float4 v = make_float4(0.f, 0.f, 0.f, 0.f);
            if (grow < Mrows) v = ((const float4*)A)[(size_t)grow * 32 + c4];
            ((float4*)sA)[f4] = v;
        }
        __syncthreads();

        unsigned long long acc[4][4];
        #pragma unroll
        for (int r = 0; r < 4; r++)
            #pragma unroll
            for (int p = 0; p < 4; p++) acc[r][p] = initc[p];

        const float* aBase = sA + (tr << 2) * FDIM;
        #pragma unroll 2
        for (int k0 = 0; k0 < FDIM; k0 += 4) {
            float4 a0 = *(const float4*)(aBase + k0);
            float4 a1 = *(const float4*)(aBase + FDIM + k0);
            float4 a2 = *(const float4*)(aBase + 2 * FDIM + k0);
            float4 a3 = *(const float4*)(aBase + 3 * FDIM + k0);
            float am[4][4] = {{a0.x, a0.y, a0.z, a0.w}, {a1.x, a1.y, a1.z, a1.w},
                              {a2.x, a2.y, a2.z, a2.w}, {a3.x, a3.y, a3.z, a3.w}};
            #pragma unroll
            for (int kk = 0; kk < 4; kk++) {
                const ulonglong2* bp = (const ulonglong2*)(sW + (k0 + kk) * FDIM + (tc << 3));
                ulonglong2 b01 = bp[0];
                ulonglong2 b23 = bp[1];
                unsigned long long bv[4] = {b01.x, b01.y, b23.x, b23.y};
                unsigned long long pa[4];
                #pragma unroll
                for (int r = 0; r < 4; r++)
                    asm("mov.b64 %0, {%1, %1};" : "=l"(pa[r]) : "f"(am[r][kk]));
                #pragma unroll
                for (int r = 0; r < 4; r++)
                    #pragma unroll
                    for (int p = 0; p < 4; p++)
                        asm("fma.rn.f32x2 %0, %1, %2, %0;"
                            : "+l"(acc[r][p]) : "l"(pa[r]), "l"(bv[p]));
            }
        }

        #pragma unroll
        for (int r = 0; r < 4; r++) {
            int grow = base + (tr << 2) + r;
            if (grow < Mrows) {
                ulonglong2* cp = (ulonglong2*)(C + (size_t)grow * FDIM + (tc << 3));
                cp[0] = make_ulonglong2(acc[r][0], acc[r][1]);
                cp[1] = make_ulonglong2(acc[r][2], acc[r][3]);
            }
        }
    }
}

// ---------------- edge scatter: agg[col] += norm * xw[row] -------------------
// one warp per edge, float4 per lane, vector reduction to L2
__global__ void k_scatter(const float* __restrict__ xw, float* __restrict__ agg,
                          const int* __restrict__ row, const int* __restrict__ col,
                          const float* __restrict__ norm) {
    int gt = blockIdx.x * blockDim.x + threadIdx.x;
    int warp = gt >> 5;
    int lane = gt & 31;
    int nw = (gridDim.x * blockDim.x) >> 5;
    for (int e = warp; e < N_EDGES; e += nw) {
        int r = __ldg(&row[e]);
        int c = __ldg(&col[e]);
        float w = __ldg(&norm[e]);
        float4 v = __ldg((const float4*)(xw + (size_t)r * FDIM) + lane);
        float* dst = agg + (size_t)c * FDIM + lane * 4;
        asm volatile("red.global.add.v4.f32 [%0], {%1,%2,%3,%4};"
                     :: "l"(dst), "f"(w * v.x), "f"(w * v.y), "f"(w * v.z), "f"(w * v.w)
                     : "memory");
    }
}

// ---------------- epilogue: t = relu(agg + dinv^2*xw + b); BN stats ----------
__global__ void k_epilogue(const float* __restrict__ agg, const float* __restrict__ xw,
                           const float* __restrict__ dinv, const float* __restrict__ bias,
                           float* __restrict__ t, float* __restrict__ gsum,
                           float* __restrict__ gsq) {
    const int tid0 = blockIdx.x * blockDim.x + threadIdx.x;
    const int stride = gridDim.x * blockDim.x;     // 65536, multiple of 32
    const int g = tid0 & 31;                       // float4 feature group
    float4 bv = ((const float4*)bias)[g];
    float s[4] = {0.f, 0.f, 0.f, 0.f}, q[4] = {0.f, 0.f, 0.f, 0.f};
    const int TOT4 = M_ROWS * 32;
    for (int i = tid0; i < TOT4; i += stride) {
        int rowM = i >> 5;
        int n = (rowM >= N_NODES) ? rowM - N_NODES : rowM;
        float d = dinv[n];
        float d2 = d * d;
        float4 a = ((const float4*)agg)[i];
        float4 xv = ((const float4*)xw)[i];
        float4 o;
        o.x = fmaxf(fmaf(d2, xv.x, a.x) + bv.x, 0.f);
        o.y = fmaxf(fmaf(d2, xv.y, a.y) + bv.y, 0.f);
        o.z = fmaxf(fmaf(d2, xv.z, a.z) + bv.z, 0.f);
        o.w = fmaxf(fmaf(d2, xv.w, a.w) + bv.w, 0.f);
        ((float4*)t)[i] = o;
        s[0] += o.x; q[0] += o.x * o.x;
        s[1] += o.y; q[1] += o.y * o.y;
        s[2] += o.z; q[2] += o.z * o.z;
        s[3] += o.w; q[3] += o.w * o.w;
    }
    __shared__ float sh[256 * 8];
    int tid = threadIdx.x;
    #pragma unroll
    for (int j = 0; j < 4; j++) { sh[tid * 8 + j] = s[j]; sh[tid * 8 + 4 + j] = q[j]; }
    __syncthreads();
    if (tid < 32) {
        float as[4] = {0.f, 0.f, 0.f, 0.f}, aq[4] = {0.f, 0.f, 0.f, 0.f};
        for (int w = 0; w < 8; w++) {
            int src = (tid + 32 * w) * 8;
            #pragma unroll
            for (int j = 0; j < 4; j++) { as[j] += sh[src + j]; aq[j] += sh[src + 4 + j]; }
        }
        #pragma unroll
        for (int j = 0; j < 4; j++) {
            atomicAdd(&gsum[4 * tid + j], as[j]);
            atomicAdd(&gsq [4 * tid + j], aq[j]);
        }
    }
}

// ---------------- fold BN into next weight matrix ----------------------------
// scale = g*rsqrt(var+eps); shift = be - mu*scale
// Wp[k][j] = scale[k]*W[k][j] ; cv[j] = (extra_bias[j]) + sum_k shift[k]*W[k][j]
__global__ void k_fold(const float* __restrict__ gsum, const float* __restrict__ gsq,
                       const float* __restrict__ gamma, const float* __restrict__ beta,
                       const float* __restrict__ Wsrc, int J,
                       const float* __restrict__ extra_bias,
                       float* __restrict__ Wp, float* __restrict__ cv) {
    __shared__ float ssc[FDIM], ssh[FDIM];
    int t = threadIdx.x;  // 128
    float mu = gsum[t] * (1.0f / M_ROWS);
    float var = gsq[t] * (1.0f / M_ROWS) - mu * mu;
    float sc = gamma[t] * rsqrtf(var + EPSBN);
    ssc[t] = sc;
    ssh[t] = beta[t] - mu * sc;
    __syncthreads();
    if (t < J) {
        float acc = extra_bias ? extra_bias[t] : 0.f;
        for (int k = 0; k < FDIM; k++) {
            float w = Wsrc[k * J + t];
            Wp[k * J + t] = ssc[k] * w;
            acc += ssh[k] * w;
        }
        cv[t] = acc;
    }
}

// ---------------- classifier: out = t2 @ Wcp + bcp ---------------------------
// warp per row; Wcp transposed in smem for conflict-free float4 reads
__global__ void k_classifier(const float* __restrict__ t2, const float* __restrict__ Wcp,
                             const float* __restrict__ bcp, float* __restrict__ out) {
    __shared__ float sWT[OUT_DIM * FDIM];  // [o][k]
    __shared__ float sb[OUT_DIM];
    int tid = threadIdx.x;  // 256
    for (int i = tid; i < FDIM * OUT_DIM; i += 256) {
        int k = i / OUT_DIM, o = i % OUT_DIM;
        sWT[o * FDIM + k] = Wcp[i];
    }
    if (tid < OUT_DIM) sb[tid] = bcp[tid];
    __syncthreads();

    int gt = blockIdx.x * blockDim.x + tid;
    int warp = gt >> 5;
    int lane = gt & 31;
    int nw = (gridDim.x * blockDim.x) >> 5;
    for (int rowM = warp; rowM < M_ROWS; rowM += nw) {
        float4 v = __ldg((const float4*)(t2 + (size_t)rowM * FDIM) + lane);
        float y[OUT_DIM];
        #pragma unroll
        for (int o = 0; o < OUT_DIM; o++) {
            float4 w = ((const float4*)(sWT + o * FDIM))[lane];
            y[o] = v.x * w.x + v.y * w.y + v.z * w.z + v.w * w.w;
        }
        #pragma unroll
        for (int off = 16; off; off >>= 1)
            #pragma unroll
            for (int o = 0; o < OUT_DIM; o++)
                y[o] += __shfl_xor_sync(0xffffffffu, y[o], off);
        if (lane < OUT_DIM) out[(size_t)rowM * OUT_DIM + lane] = y[lane] + sb[lane];
    }
}

// ---------------- launch -----------------------------------------------------
extern "C" void kernel_launch(void* const* d_in, const int* in_sizes, int n_in,
                              void* d_out, int out_size) {
    const float* x   = (const float*)d_in[0];
    const int*   ei  = (const int*)d_in[1];
    const float* ewp = (const float*)d_in[2];
    const float* W1  = (const float*)d_in[3];
    const float* b1  = (const float*)d_in[4];
    const float* W2  = (const float*)d_in[5];
    const float* b2  = (const float*)d_in[6];
    const float* g1  = (const float*)d_in[7];
    const float* be1 = (const float*)d_in[8];
    const float* g2  = (const float*)d_in[9];
    const float* be2 = (const float*)d_in[10];
    const float* Wc  = (const float*)d_in[11];
    const float* bc  = (const float*)d_in[12];
    float* out = (float*)d_out;
    const int* row = ei;
    const int* col = ei + N_EDGES;

    float *p_xw, *p_agg, *p_t, *p_norm, *p_dinv, *p_deg;
    float *p_W2p, *p_cvec, *p_Wcp, *p_bcp, *p_sum, *p_sq;
    cudaGetSymbolAddress((void**)&p_xw,  g_xw);
    cudaGetSymbolAddress((void**)&p_agg, g_agg);
    cudaGetSymbolAddress((void**)&p_t,   g_t);
    cudaGetSymbolAddress((void**)&p_norm, g_norm);
    cudaGetSymbolAddress((void**)&p_dinv, g_dinv);
    cudaGetSymbolAddress((void**)&p_deg,  g_deg);
    cudaGetSymbolAddress((void**)&p_W2p,  g_W2p);
    cudaGetSymbolAddress((void**)&p_cvec, g_cvec);
    cudaGetSymbolAddress((void**)&p_Wcp,  g_Wcp);
    cudaGetSymbolAddress((void**)&p_bcp,  g_bcp);
    cudaGetSymbolAddress((void**)&p_sum,  g_sum);
    cudaGetSymbolAddress((void**)&p_sq,   g_sq);

    (void)cudaFuncSetAttribute(k_gemm128, cudaFuncAttributeMaxDynamicSharedMemorySize, 98304);

    const size_t actBytes = (size_t)M_ROWS * FDIM * sizeof(float);

    // --- normalization coefficients ---
    k_init_deg  <<<(N_NODES + 255) / 256, 256>>>(p_deg);
    k_accum_deg <<<(N_EDGES + 255) / 256, 256>>>(ewp, col, p_deg);
    k_dinv      <<<(N_NODES + 255) / 256, 256>>>(p_deg, p_dinv);
    k_norm      <<<(N_EDGES + 255) / 256, 256>>>(ewp, row, col, p_dinv, p_norm);

    // --- layer 1 ---
    k_gemm128<<<592, 256, 98304>>>(x, W1, nullptr, p_xw, M_ROWS);
    cudaMemsetAsync(p_agg, 0, actBytes, 0);
    k_scatter<<<1024, 256>>>(p_xw, p_agg, row, col, p_norm);                          // batch 0
    k_scatter<<<1024, 256>>>(p_xw + (size_t)N_NODES * FDIM,
                             p_agg + (size_t)N_NODES * FDIM, row, col, p_norm);       // batch 1
    cudaMemsetAsync(p_sum, 0, FDIM * sizeof(float), 0);
    cudaMemsetAsync(p_sq,  0, FDIM * sizeof(float), 0);
    k_epilogue<<<256, 256>>>(p_agg, p_xw, p_dinv, b1, p_t, p_sum, p_sq);
    k_fold<<<1, 128>>>(p_sum, p_sq, g1, be1, W2, FDIM, nullptr, p_W2p, p_cvec);

    // --- layer 2 (BN1 folded into W2) ---
    k_gemm128<<<592, 256, 98304>>>(p_t, p_W2p, p_cvec, p_xw, M_ROWS);
    cudaMemsetAsync(p_agg, 0, actBytes, 0);
    k_scatter<<<1024, 256>>>(p_xw, p_agg, row, col, p_norm);
    k_scatter<<<1024, 256>>>(p_xw + (size_t)N_NODES * FDIM,
                             p_agg + (size_t)N_NODES * FDIM, row, col, p_norm);
    cudaMemsetAsync(p_sum, 0, FDIM * sizeof(float), 0);
    cudaMemsetAsync(p_sq,  0, FDIM * sizeof(float), 0);
    k_epilogue<<<256, 256>>>(p_agg, p_xw, p_dinv, b2, p_t, p_sum, p_sq);
    k_fold<<<1, 128>>>(p_sum, p_sq, g2, be2, Wc, OUT_DIM, bc, p_Wcp, p_bcp);

    // --- classifier (BN2 folded into Wc) ---
    k_classifier<<<1024, 256>>>(p_t, p_Wcp, p_bcp, out);
}